// round 12
// baseline (speedup 1.0000x reference)
#include <cuda_runtime.h>
#include <math.h>

// Persistent single kernel, super-tile staged to cut DRAM traffic:
// for each ~90MB super-tile (fits in 126MB L2):
//   phase a: read tile from DRAM with evict_last policy (pin in L2),
//            grid barrier, compute tile max m_S
//   phase b: quantize tile with e_S = floor(log2(m_S)), re-reading via
//            evict_first policy (demote after use); stores evict_first too.
// e_glob = max_S e_S, so if all e_S agree the speculative output is exact.
// If they ever disagree (uniform, replay-deterministic decision), one extra
// barrier + full re-quantize with e_glob restores exactness.
// sm_103a note: inline .L2::evict_* is only legal on 256-bit accesses, so we
// use createpolicy + ld/st.global.L2::cache_hint on the 128-bit path.
// Grid = one wave (148 SMs x 8 CTAs, launch_bounds(256,8)) -> co-resident,
// ticket barrier cannot deadlock; counter only grows -> replay-safe.
#define NCTA 1184
#define THREADS 256
#define NSUP 6

__device__ float g_part[NSUP][NCTA];
__device__ unsigned g_ticket;   // zero-init; grows monotonically across replays

__device__ __forceinline__ float warp_max(float m) {
    #pragma unroll
    for (int o = 16; o > 0; o >>= 1)
        m = fmaxf(m, __shfl_xor_sync(0xffffffffu, m, o));
    return m;
}

__device__ __forceinline__ unsigned long long mk_policy_evict_last() {
    unsigned long long p;
    asm volatile("createpolicy.fractional.L2::evict_last.b64 %0, 1.0;" : "=l"(p));
    return p;
}
__device__ __forceinline__ unsigned long long mk_policy_evict_first() {
    unsigned long long p;
    asm volatile("createpolicy.fractional.L2::evict_first.b64 %0, 1.0;" : "=l"(p));
    return p;
}

__device__ __forceinline__ float4 ld_hint4(const float4* p, unsigned long long pol) {
    float4 v;
    asm volatile("ld.global.L2::cache_hint.v4.f32 {%0,%1,%2,%3}, [%4], %5;"
                 : "=f"(v.x), "=f"(v.y), "=f"(v.z), "=f"(v.w) : "l"(p), "l"(pol));
    return v;
}
__device__ __forceinline__ void st_hint4(float4* p, float4 v, unsigned long long pol) {
    asm volatile("st.global.L2::cache_hint.v4.f32 [%0], {%1,%2,%3,%4}, %5;"
                 :: "l"(p), "f"(v.x), "f"(v.y), "f"(v.z), "f"(v.w), "l"(pol) : "memory");
}

__device__ __forceinline__ float max4(float4 v) {
    return fmaxf(fmaxf(fabsf(v.x), fabsf(v.y)), fmaxf(fabsf(v.z), fabsf(v.w)));
}

__device__ __forceinline__ float bq_quant_one(float v, float s, float inv_s) {
    v = (v >= 0.0f) ? fmaxf(v, 1e-10f) : fminf(v, -1e-10f);  // zeros -> +1e-10
    float i = rintf(v * s);                                   // half-to-even
    i = fminf(fmaxf(i, -128.0f), 127.0f);                     // clip to int8 range
    return i * inv_s;                                         // exact pow2 scale
}

__device__ __forceinline__ float4 quant4(float4 v, float s, float inv_s) {
    v.x = bq_quant_one(v.x, s, inv_s);
    v.y = bq_quant_one(v.y, s, inv_s);
    v.z = bq_quant_one(v.z, s, inv_s);
    v.w = bq_quant_one(v.w, s, inv_s);
    return v;
}

__device__ __forceinline__ void grid_barrier_t0() {
    // call with all threads; t0 spins, others held by the trailing sync
    if (threadIdx.x == 0) {
        __threadfence();                      // release prior global writes
        unsigned t = atomicAdd(&g_ticket, 1u);
        unsigned target = (t / NCTA + 1u) * NCTA;
        for (;;) {
            unsigned cur;
            asm volatile("ld.global.acquire.gpu.u32 %0, [%1];"
                         : "=r"(cur) : "l"(&g_ticket));
            if (cur >= target) break;
            __nanosleep(64);
        }
    }
    __syncthreads();
}

__global__ void __launch_bounds__(THREADS, 8)
bq_fused_kernel(const float4* __restrict__ x, float4* __restrict__ y,
                unsigned nvec,
                const float* __restrict__ xs, float* __restrict__ ys,
                unsigned ntail_base, unsigned ntail) {
    __shared__ float sh_w[THREADS / 32];
    __shared__ float sh_b;

    const unsigned stride = NCTA * THREADS;
    const unsigned t0 = blockIdx.x * THREADS + threadIdx.x;
    const unsigned sv = (nvec + NSUP - 1u) / NSUP;
    const int lane = threadIdx.x & 31;
    const int w = threadIdx.x >> 5;

    const unsigned long long pol_last  = mk_policy_evict_last();
    const unsigned long long pol_first = mk_policy_evict_first();

    float gm = 0.0f;
    int e0 = 0;
    bool all_same = true;

    #pragma unroll 1
    for (int sidx = 0; sidx < NSUP; ++sidx) {
        unsigned lo = (unsigned)sidx * sv;
        unsigned hi = lo + sv;
        if (hi > nvec) hi = nvec;
        if (lo > nvec) lo = nvec;

        // ---- phase a: tile max (DRAM reads, pinned in L2 via evict_last) ----
        float m = 0.0f;
        for (unsigned i = lo + t0; i < hi; i += stride)
            m = fmaxf(m, max4(ld_hint4(&x[i], pol_last)));
        if (sidx == NSUP - 1 && blockIdx.x == 0 && threadIdx.x < ntail)
            m = fmaxf(m, fabsf(xs[ntail_base + threadIdx.x]));

        m = warp_max(m);
        if (lane == 0) sh_w[w] = m;
        __syncthreads();
        if (w == 0) {
            m = (lane < THREADS / 32) ? sh_w[lane] : 0.0f;
            m = warp_max(m);
            if (lane == 0) g_part[sidx][blockIdx.x] = m;
        }
        grid_barrier_t0();

        // ---- tile max over all CTAs (partials L2-resident) ----
        float mm = 0.0f;
        for (unsigned p = threadIdx.x; p < NCTA; p += THREADS)
            mm = fmaxf(mm, __ldcg(&g_part[sidx][p]));
        mm = warp_max(mm);
        if (lane == 0) sh_w[w] = mm;
        __syncthreads();
        if (threadIdx.x == 0) {
            mm = sh_w[0];
            #pragma unroll
            for (int k = 1; k < THREADS / 32; ++k) mm = fmaxf(mm, sh_w[k]);
            sh_b = mm;
        }
        __syncthreads();
        mm = sh_b;

        gm = fmaxf(gm, mm);
        float maxv = fmaxf(mm, 1e-10f);       // clamp can only raise tiny maxima
        float e = fminf(fmaxf(floorf(log2f(maxv)), -128.0f), 127.0f);
        int ei = (int)e;
        if (sidx == 0) e0 = ei;
        else all_same = all_same && (ei == e0);
        float sS  = exp2f(6.0f - e);          // 2^(-e + (bits-2)), bits=8
        float ivS = exp2f(e - 6.0f);

        // ---- phase b: quantize tile (reads hit L2; demote after use) ----
        for (unsigned i = lo + t0; i < hi; i += stride)
            st_hint4(&y[i], quant4(ld_hint4(&x[i], pol_first), sS, ivS), pol_first);
    }

    // ---- global exponent; fixup only if any tile exponent differed ----
    float maxg = fmaxf(gm, 1e-10f);
    float eg = fminf(fmaxf(floorf(log2f(maxg)), -128.0f), 127.0f);
    float sG  = exp2f(6.0f - eg);
    float ivG = exp2f(eg - 6.0f);

    if (!all_same) {   // identical decision in every CTA -> collective barrier is safe
        grid_barrier_t0();
        for (unsigned i = t0; i < nvec; i += stride)
            y[i] = quant4(x[i], sG, ivG);
    }

    if (blockIdx.x == 0 && threadIdx.x < ntail)
        ys[ntail_base + threadIdx.x] =
            bq_quant_one(xs[ntail_base + threadIdx.x], sG, ivG);
}

extern "C" void kernel_launch(void* const* d_in, const int* in_sizes, int n_in,
                              void* d_out, int out_size) {
    const float* x = (const float*)d_in[0];
    float* y = (float*)d_out;
    unsigned n = (unsigned)in_sizes[0];
    unsigned nvec = n >> 2;
    unsigned ntail_base = nvec << 2;
    unsigned ntail = n - ntail_base;

    bq_fused_kernel<<<NCTA, THREADS>>>(
        (const float4*)x, (float4*)y, nvec, x, y, ntail_base, ntail);
}

// round 13
// speedup vs baseline: 1.3769x; 1.3769x over previous
#include <cuda_runtime.h>
#include <math.h>

// SPECULATIVE SINGLE-PASS block quantize.
// The only global dependency is e = floor(log2(max|x|)). A sample max is
// always <= the global max, so an exponent speculated from a sample can only
// undershoot -- and the main pass computes the TRUE max as it streams, so an
// undershoot is detected and fixed by an in-place requantize (uniform branch,
// never taken for this data: P(sample exponent != global exponent) ~ e^-300).
//   phase 0 (~3us):  coalesced decimated sample (every 32nd stripe) -> e_spec
//   phase 1 (~165us): ONE pass: read x, track max, quantize w/ e_spec, write y
//                     => 1.0 GB of DRAM traffic instead of 1.5 GB
//   phase 2 (rare):   if e_glob != e_spec, requantize in place (same thread ->
//                     same elements, no cross-CTA hazard, no barrier needed)
// Grid = one wave (148 SMs x 8 CTAs, launch_bounds(256,8)) -> co-resident;
// ticket barrier cannot deadlock; counter only grows -> graph-replay-safe.
#define NCTA 1184
#define THREADS 256
#define DECIM 32          // sample every 32nd stripe (~16 MB total, coalesced)

__device__ float g_samp[NCTA];
__device__ float g_full[NCTA];
__device__ unsigned g_ticket;   // zero-init; grows monotonically across replays

__device__ __forceinline__ float warp_max(float m) {
    #pragma unroll
    for (int o = 16; o > 0; o >>= 1)
        m = fmaxf(m, __shfl_xor_sync(0xffffffffu, m, o));
    return m;
}

__device__ __forceinline__ float block_reduce_max(float m) {
    __shared__ float sm[THREADS / 32];
    m = warp_max(m);
    int lane = threadIdx.x & 31;
    int w = threadIdx.x >> 5;
    if (lane == 0) sm[w] = m;
    __syncthreads();
    if (w == 0) {
        m = (lane < (THREADS / 32)) ? sm[lane] : 0.0f;
        m = warp_max(m);
    }
    return m;  // valid in warp 0
}

__device__ __forceinline__ float max4(float4 v) {
    return fmaxf(fmaxf(fabsf(v.x), fabsf(v.y)), fmaxf(fabsf(v.z), fabsf(v.w)));
}

__device__ __forceinline__ float bq_quant_one(float v, float s, float inv_s) {
    v = (v >= 0.0f) ? fmaxf(v, 1e-10f) : fminf(v, -1e-10f);  // zeros -> +1e-10
    float i = rintf(v * s);                                   // half-to-even
    i = fminf(fmaxf(i, -128.0f), 127.0f);                     // clip to int8 range
    return i * inv_s;                                         // exact pow2 scale
}

__device__ __forceinline__ float4 quant4(float4 v, float s, float inv_s) {
    v.x = bq_quant_one(v.x, s, inv_s);
    v.y = bq_quant_one(v.y, s, inv_s);
    v.z = bq_quant_one(v.z, s, inv_s);
    v.w = bq_quant_one(v.w, s, inv_s);
    return v;
}

__device__ __forceinline__ void grid_barrier_t0() {
    // call with all threads of every CTA; t0 spins, rest held by the sync
    if (threadIdx.x == 0) {
        __threadfence();                      // release prior global writes
        unsigned t = atomicAdd(&g_ticket, 1u);
        unsigned target = (t / NCTA + 1u) * NCTA;
        for (;;) {
            unsigned cur;
            asm volatile("ld.global.acquire.gpu.u32 %0, [%1];"
                         : "=r"(cur) : "l"(&g_ticket));
            if (cur >= target) break;
            __nanosleep(64);
        }
    }
    __syncthreads();
}

// exponent clip + scales from a raw max
__device__ __forceinline__ float exp_from_max(float m) {
    float maxv = fmaxf(m, 1e-10f);           // 1e-10 clamp can only raise tiny maxima
    return fminf(fmaxf(floorf(log2f(maxv)), -128.0f), 127.0f);
}

__global__ void __launch_bounds__(THREADS, 8)
bq_spec_kernel(const float4* __restrict__ x, float4* __restrict__ y,
               unsigned nvec,
               const float* __restrict__ xs, float* __restrict__ ys,
               unsigned ntail_base, unsigned ntail) {
    __shared__ float sh_b;

    const unsigned stride = NCTA * THREADS;
    const unsigned t0 = blockIdx.x * THREADS + threadIdx.x;

    // ---- phase 0: decimated sample (coalesced: full warps, every DECIM-th
    //      stripe). Sample max <= global max always. ----
    float ms = 0.0f;
    for (unsigned i = t0; i < nvec; i += stride * DECIM)
        ms = fmaxf(ms, max4(x[i]));
    ms = block_reduce_max(ms);
    if (threadIdx.x == 0) g_samp[blockIdx.x] = ms;
    grid_barrier_t0();

    {
        float mm = 0.0f;
        for (unsigned p = threadIdx.x; p < NCTA; p += THREADS)
            mm = fmaxf(mm, __ldcg(&g_samp[p]));
        mm = block_reduce_max(mm);
        if (threadIdx.x == 0) sh_b = mm;
        __syncthreads();
    }
    const float e_spec = exp_from_max(sh_b);
    const float s_spec  = exp2f(6.0f - e_spec);   // 2^(-e + (bits-2)), bits=8
    const float iv_spec = exp2f(e_spec - 6.0f);

    // ---- phase 1: single fused pass -- read once, track true max,
    //      quantize speculatively, write y ----
    float m = 0.0f;
    for (unsigned i = t0; i < nvec; i += stride) {
        float4 v = x[i];
        m = fmaxf(m, max4(v));
        y[i] = quant4(v, s_spec, iv_spec);
    }
    if (blockIdx.x == 0 && threadIdx.x < ntail) {
        float vt = xs[ntail_base + threadIdx.x];
        m = fmaxf(m, fabsf(vt));
        ys[ntail_base + threadIdx.x] = bq_quant_one(vt, s_spec, iv_spec);
    }

    m = block_reduce_max(m);
    if (threadIdx.x == 0) g_full[blockIdx.x] = m;
    grid_barrier_t0();

    {
        float mm = 0.0f;
        for (unsigned p = threadIdx.x; p < NCTA; p += THREADS)
            mm = fmaxf(mm, __ldcg(&g_full[p]));
        mm = block_reduce_max(mm);
        if (threadIdx.x == 0) sh_b = mm;
        __syncthreads();
    }
    const float e_glob = exp_from_max(sh_b);

    // ---- phase 2: fixup (uniform branch; each thread rewrites exactly the
    //      elements it wrote in phase 1 -> no hazard, no barrier) ----
    if (e_glob != e_spec) {
        const float s_g  = exp2f(6.0f - e_glob);
        const float iv_g = exp2f(e_glob - 6.0f);
        for (unsigned i = t0; i < nvec; i += stride)
            y[i] = quant4(x[i], s_g, iv_g);
        if (blockIdx.x == 0 && threadIdx.x < ntail)
            ys[ntail_base + threadIdx.x] =
                bq_quant_one(xs[ntail_base + threadIdx.x], s_g, iv_g);
    }
}

extern "C" void kernel_launch(void* const* d_in, const int* in_sizes, int n_in,
                              void* d_out, int out_size) {
    const float* x = (const float*)d_in[0];
    float* y = (float*)d_out;
    unsigned n = (unsigned)in_sizes[0];
    unsigned nvec = n >> 2;
    unsigned ntail_base = nvec << 2;
    unsigned ntail = n - ntail_base;

    bq_spec_kernel<<<NCTA, THREADS>>>(
        (const float4*)x, (float4*)y, nvec, x, y, ntail_base, ntail);
}